// round 12
// baseline (speedup 1.0000x reference)
#include <cuda_runtime.h>
#include <cuda_fp16.h>
#include <cstdint>
#include <cstddef>

#define T_TOK 1024
#define HID   2048
#define IDIM  1024
#define NEXP  32
#define NGRP  8
#define EPG   4
#define TOPG  4
#define TOPK  8
#define NE    33      // 32 routed + 1 shared
#define CAP   1024
#define RSCALE 2.5f

// GEMM tiling
#define BK    64                 // k-chunk
#define STR   72                 // padded fp16 row stride (144B -> conflict-free ldmatrix)
#define TILEB (128 * STR * 2)    // bytes per 128xBK fp16 tile = 18432
#define BUFB  (2 * TILEB)        // A, B = 36864
#define SMEMB (2 * BUFB)         // double buffer = 73728

// ---------------- static scratch (no allocations allowed) ----------------
__device__ float  g_combine[T_TOK * NEXP];
__device__ int    g_count[NE];
__device__ int    g_token[NE * CAP];
__device__ float  g_wt[NE * CAP];
__device__ int    g_rowid[NEXP * T_TOK];                    // [e][t] -> row or -1
__device__ __half g_act[(size_t)NE * CAP * IDIM];           // silu(g)*u rows (fp16)
__device__ float  g_down[(size_t)NE * CAP * HID];           // weighted down-proj rows

__device__ __forceinline__ float silu_f(float v) {
    return v / (1.0f + expf(-v));
}

__device__ __forceinline__ uint32_t smem_u32(const void* p) {
    uint32_t a;
    asm("{ .reg .u64 t; cvta.to.shared.u64 t, %1; cvt.u32.u64 %0, t; }"
        : "=r"(a) : "l"(p));
    return a;
}

__device__ __forceinline__ void ldm4(uint32_t* r, uint32_t addr) {
    asm volatile("ldmatrix.sync.aligned.m8n8.x4.shared.b16 {%0,%1,%2,%3}, [%4];"
        : "=r"(r[0]), "=r"(r[1]), "=r"(r[2]), "=r"(r[3]) : "r"(addr));
}
__device__ __forceinline__ void mma16816h(float* c, const uint32_t* a, const uint32_t* b) {
    asm volatile("mma.sync.aligned.m16n8k16.row.col.f32.f16.f16.f32 "
        "{%0,%1,%2,%3}, {%4,%5,%6,%7}, {%8,%9}, {%0,%1,%2,%3};"
        : "+f"(c[0]), "+f"(c[1]), "+f"(c[2]), "+f"(c[3])
        : "r"(a[0]), "r"(a[1]), "r"(a[2]), "r"(a[3]), "r"(b[0]), "r"(b[1]));
}

// fp32x4 -> fp16, store 8B
__device__ __forceinline__ void store_h(uint32_t a, float4 v) {
    __half h0 = __float2half_rn(v.x), h1 = __float2half_rn(v.y);
    __half h2 = __float2half_rn(v.z), h3 = __float2half_rn(v.w);
    unsigned long long H =
        (unsigned long long)__half_as_ushort(h0) |
        ((unsigned long long)__half_as_ushort(h1) << 16) |
        ((unsigned long long)__half_as_ushort(h2) << 32) |
        ((unsigned long long)__half_as_ushort(h3) << 48);
    asm volatile("st.shared.b64 [%0], %1;" :: "r"(a), "l"(H) : "memory");
}

__device__ __forceinline__ void store_v4(uint32_t a, uint4 v) {
    asm volatile("st.shared.v4.b32 [%0], {%1,%2,%3,%4};"
        :: "r"(a), "r"(v.x), "r"(v.y), "r"(v.z), "r"(v.w) : "memory");
}

// ---------------- 1) router ----------------
__global__ void router_kernel(const float* __restrict__ x,
                              const float* __restrict__ gw,
                              const float* __restrict__ bias) {
    __shared__ float sx[HID];
    __shared__ float slog[NEXP];
    int t = blockIdx.x;
    const float* xr = x + (size_t)t * HID;
    for (int k = threadIdx.x; k < HID; k += blockDim.x) sx[k] = xr[k];
    __syncthreads();
    int warp = threadIdx.x >> 5, lane = threadIdx.x & 31;
    for (int e = warp; e < NEXP; e += 8) {
        const float* w = gw + (size_t)e * HID;
        float acc = 0.f;
        for (int k = lane; k < HID; k += 32) acc = fmaf(sx[k], w[k], acc);
        #pragma unroll
        for (int o = 16; o; o >>= 1) acc += __shfl_down_sync(0xffffffffu, acc, o);
        if (lane == 0) slog[e] = acc;
    }
    __syncthreads();
    if (threadIdx.x == 0) {
        float s[NEXP], sr[NEXP];
        #pragma unroll
        for (int e = 0; e < NEXP; e++) {
            float sc = 1.f / (1.f + expf(-slog[e]));
            s[e] = sc;
            sr[e] = sc + bias[e];
        }
        float gs[NGRP];
        #pragma unroll
        for (int g = 0; g < NGRP; g++) {
            float m1 = -1e30f, m2 = -1e30f;
            #pragma unroll
            for (int j = 0; j < EPG; j++) {
                float v = sr[g * EPG + j];
                if (v > m1) { m2 = m1; m1 = v; }
                else if (v > m2) { m2 = v; }
            }
            gs[g] = m1 + m2;
        }
        bool gsel[NGRP];
        #pragma unroll
        for (int g = 0; g < NGRP; g++) gsel[g] = false;
        for (int it = 0; it < TOPG; it++) {
            float best = -1e30f; int bi = 0;
            for (int g = 0; g < NGRP; g++)
                if (!gsel[g] && gs[g] > best) { best = gs[g]; bi = g; }
            gsel[bi] = true;
        }
        bool taken[NEXP];
        #pragma unroll
        for (int e = 0; e < NEXP; e++) taken[e] = false;
        int ids[TOPK];
        for (int it = 0; it < TOPK; it++) {
            float best = -1e30f; int bi = 0;
            for (int e = 0; e < NEXP; e++)
                if (gsel[e >> 2] && !taken[e] && sr[e] > best) { best = sr[e]; bi = e; }
            taken[bi] = true;
            ids[it] = bi;
        }
        float sum = 0.f;
        for (int k = 0; k < TOPK; k++) sum += s[ids[k]];
        float inv = RSCALE / (sum + 1e-20f);
        float out[NEXP];
        #pragma unroll
        for (int e = 0; e < NEXP; e++) out[e] = 0.f;
        for (int k = 0; k < TOPK; k++) out[ids[k]] = s[ids[k]] * inv;
        #pragma unroll
        for (int e = 0; e < NEXP; e++) g_combine[t * NEXP + e] = out[e];
    }
}

// ---------------- 2) compact per-expert token lists ----------------
__global__ void build_lists_kernel() {
    int e = blockIdx.x;
    int t = threadIdx.x;
    __shared__ int sc[T_TOK];
    float w;
    int flag;
    if (e < NEXP) {
        w = g_combine[t * NEXP + e];
        flag = (w > 0.f) ? 1 : 0;
    } else {
        w = 1.0f;
        flag = 1;
    }
    sc[t] = flag;
    __syncthreads();
    for (int off = 1; off < T_TOK; off <<= 1) {
        int v = (t >= off) ? sc[t - off] : 0;
        __syncthreads();
        sc[t] += v;
        __syncthreads();
    }
    int pos = sc[t] - flag;
    if (flag) {
        g_token[e * CAP + pos] = t;
        g_wt[e * CAP + pos] = w;
    }
    if (e < NEXP) g_rowid[e * T_TOK + t] = flag ? (e * CAP + pos) : -1;
    if (t == T_TOK - 1) g_count[e] = sc[T_TOK - 1];
}

// ---------------- 3) gate_up GEMM via fp16 mma.sync (single term) ----------
// CTA tile: M=128 rows, D = 128 cols interleaved (even=gate j, odd=up j).
// 512 threads = 16 warps of 32x32; BK=64, double buffered.
__global__ void __launch_bounds__(512, 1)
gateup_mma(const float* __restrict__ x,
           const float* __restrict__ wgu,
           const float* __restrict__ sgu) {
    int e = blockIdx.z;
    int cnt = g_count[e];
    int m0 = blockIdx.x * 128;
    if (m0 >= cnt) return;
    int n0 = blockIdx.y * 64;
    const float* W = (e < NEXP) ? (wgu + (size_t)e * (2 * IDIM) * HID) : sgu;

    extern __shared__ char smem[];
    uint32_t sb = smem_u32(smem);
    int tid = threadIdx.x;
    int lane = tid & 31, wid = tid >> 5;

    // loader: 4 threads per tile row, each covers 16 floats of the 64-float chunk
    int lrow = tid >> 2, lquad = tid & 3;
    int mrow = m0 + lrow; if (mrow > cnt - 1) mrow = cnt - 1;
    const float* aptr = x + (size_t)g_token[e * CAP + mrow] * HID + lquad * 16;
    int jcol = lrow >> 1;
    int wrow = (lrow & 1) ? (IDIM + n0 + jcol) : (n0 + jcol);
    const float* bptr = W + (size_t)wrow * HID + lquad * 16;
    uint32_t soff = (uint32_t)(lrow * STR + lquad * 16) * 2;

    // warp grid 4x4: each warp 32 rows x 32 cols
    int wm0 = (wid >> 2) * 32, wn0 = (wid & 3) * 32;
    uint32_t a_r = (uint32_t)(wm0 + (lane & 15));
    uint32_t a_c8 = (uint32_t)((lane >> 4) * 8);
    uint32_t b_row = (uint32_t)((lane & 7) + ((lane >> 4) << 3));
    uint32_t b_k8 = (uint32_t)(((lane >> 3) & 1) * 8);

    float acc[2][4][4];
    #pragma unroll
    for (int mi = 0; mi < 2; mi++)
        #pragma unroll
        for (int ni = 0; ni < 4; ni++)
            #pragma unroll
            for (int q = 0; q < 4; q++) acc[mi][ni][q] = 0.f;

    float4 ra[4], rb[4];
    #pragma unroll
    for (int q = 0; q < 4; q++) {
        ra[q] = *(const float4*)(aptr + q * 4);
        rb[q] = *(const float4*)(bptr + q * 4);
    }
    #pragma unroll
    for (int q = 0; q < 4; q++) {
        uint32_t o = soff + q * 8;
        store_h(sb + o, ra[q]);
        store_h(sb + TILEB + o, rb[q]);
    }
    __syncthreads();

    const int NC = HID / BK;  // 32
    for (int c = 0; c < NC; c++) {
        if (c + 1 < NC) {
            const float* ap = aptr + (c + 1) * BK;
            const float* bp = bptr + (c + 1) * BK;
            #pragma unroll
            for (int q = 0; q < 4; q++) {
                ra[q] = *(const float4*)(ap + q * 4);
                rb[q] = *(const float4*)(bp + q * 4);
            }
        }
        uint32_t cur = sb + (uint32_t)(c & 1) * BUFB;
        #pragma unroll
        for (int kh = 0; kh < 4; kh++) {
            uint32_t ah[2][4], bh[2][4];
            #pragma unroll
            for (int mi = 0; mi < 2; mi++) {
                uint32_t ad = cur + ((a_r + mi * 16) * STR + kh * 16 + a_c8) * 2;
                ldm4(ah[mi], ad);
            }
            #pragma unroll
            for (int nj = 0; nj < 2; nj++) {
                uint32_t bd = cur + TILEB +
                    ((wn0 + nj * 16 + b_row) * STR + kh * 16 + b_k8) * 2;
                ldm4(bh[nj], bd);
            }
            #pragma unroll
            for (int mi = 0; mi < 2; mi++)
                #pragma unroll
                for (int ni = 0; ni < 4; ni++) {
                    const uint32_t* bhp = &bh[ni >> 1][(ni & 1) * 2];
                    mma16816h(acc[mi][ni], ah[mi], bhp);
                }
        }
        if (c + 1 < NC) {
            uint32_t nb = sb + (uint32_t)((c + 1) & 1) * BUFB;
            #pragma unroll
            for (int q = 0; q < 4; q++) {
                uint32_t o = soff + q * 8;
                store_h(nb + o, ra[q]);
                store_h(nb + TILEB + o, rb[q]);
            }
        }
        __syncthreads();
    }

    // epilogue: c0=gate, c1=up for col j; rows g and g+8 -> fp16 g_act
    int g = lane >> 2, tc = (lane & 3) * 2;
    #pragma unroll
    for (int mi = 0; mi < 2; mi++) {
        int r0 = m0 + wm0 + mi * 16 + g;
        int r1 = r0 + 8;
        #pragma unroll
        for (int ni = 0; ni < 4; ni++) {
            int col = n0 + ((wn0 + ni * 8 + tc) >> 1);
            if (r0 < cnt)
                g_act[((size_t)e * CAP + r0) * IDIM + col] =
                    __float2half_rn(silu_f(acc[mi][ni][0]) * acc[mi][ni][1]);
            if (r1 < cnt)
                g_act[((size_t)e * CAP + r1) * IDIM + col] =
                    __float2half_rn(silu_f(acc[mi][ni][2]) * acc[mi][ni][3]);
        }
    }
}

// ---------------- 4) down GEMM via fp16 mma.sync (single term), weighted ----
__global__ void __launch_bounds__(512, 1)
down_mma(const float* __restrict__ wdn,
         const float* __restrict__ sdn) {
    int e = blockIdx.z;
    int cnt = g_count[e];
    int m0 = blockIdx.x * 128;
    if (m0 >= cnt) return;
    int n0 = blockIdx.y * 128;
    const float* W = (e < NEXP) ? (wdn + (size_t)e * HID * IDIM) : sdn;

    extern __shared__ char smem[];
    uint32_t sb = smem_u32(smem);
    int tid = threadIdx.x;
    int lane = tid & 31, wid = tid >> 5;

    int lrow = tid >> 2, lquad = tid & 3;
    int mrow = m0 + lrow; if (mrow > cnt - 1) mrow = cnt - 1;
    // A is already fp16 in g_act: load 16 halves (2x uint4) per thread per chunk
    const uint4* aptr = (const uint4*)(g_act + ((size_t)e * CAP + mrow) * IDIM + lquad * 16);
    const float* bptr = W + (size_t)(n0 + lrow) * IDIM + lquad * 16;
    uint32_t soff = (uint32_t)(lrow * STR + lquad * 16) * 2;

    int wm0 = (wid >> 2) * 32, wn0 = (wid & 3) * 32;
    uint32_t a_r = (uint32_t)(wm0 + (lane & 15));
    uint32_t a_c8 = (uint32_t)((lane >> 4) * 8);
    uint32_t b_row = (uint32_t)((lane & 7) + ((lane >> 4) << 3));
    uint32_t b_k8 = (uint32_t)(((lane >> 3) & 1) * 8);

    float acc[2][4][4];
    #pragma unroll
    for (int mi = 0; mi < 2; mi++)
        #pragma unroll
        for (int ni = 0; ni < 4; ni++)
            #pragma unroll
            for (int q = 0; q < 4; q++) acc[mi][ni][q] = 0.f;

    uint4 raH[2];
    float4 rb[4];
    raH[0] = aptr[0];
    raH[1] = aptr[1];
    #pragma unroll
    for (int q = 0; q < 4; q++) rb[q] = *(const float4*)(bptr + q * 4);
    store_v4(sb + soff, raH[0]);
    store_v4(sb + soff + 16, raH[1]);
    #pragma unroll
    for (int q = 0; q < 4; q++) store_h(sb + TILEB + soff + q * 8, rb[q]);
    __syncthreads();

    const int NC = IDIM / BK;  // 16
    for (int c = 0; c < NC; c++) {
        if (c + 1 < NC) {
            const uint4* ap = aptr + (c + 1) * (BK / 8);
            const float* bp = bptr + (c + 1) * BK;
            raH[0] = ap[0];
            raH[1] = ap[1];
            #pragma unroll
            for (int q = 0; q < 4; q++) rb[q] = *(const float4*)(bp + q * 4);
        }
        uint32_t cur = sb + (uint32_t)(c & 1) * BUFB;
        #pragma unroll
        for (int kh = 0; kh < 4; kh++) {
            uint32_t ah[2][4], bh[2][4];
            #pragma unroll
            for (int mi = 0; mi < 2; mi++) {
                uint32_t ad = cur + ((a_r + mi * 16) * STR + kh * 16 + a_c8) * 2;
                ldm4(ah[mi], ad);
            }
            #pragma unroll
            for (int nj = 0; nj < 2; nj++) {
                uint32_t bd = cur + TILEB +
                    ((wn0 + nj * 16 + b_row) * STR + kh * 16 + b_k8) * 2;
                ldm4(bh[nj], bd);
            }
            #pragma unroll
            for (int mi = 0; mi < 2; mi++)
                #pragma unroll
                for (int ni = 0; ni < 4; ni++) {
                    const uint32_t* bhp = &bh[ni >> 1][(ni & 1) * 2];
                    mma16816h(acc[mi][ni], ah[mi], bhp);
                }
        }
        if (c + 1 < NC) {
            uint32_t nb = sb + (uint32_t)((c + 1) & 1) * BUFB;
            store_v4(nb + soff, raH[0]);
            store_v4(nb + soff + 16, raH[1]);
            #pragma unroll
            for (int q = 0; q < 4; q++) store_h(nb + TILEB + soff + q * 8, rb[q]);
        }
        __syncthreads();
    }

    int g = lane >> 2, tc = (lane & 3) * 2;
    #pragma unroll
    for (int mi = 0; mi < 2; mi++) {
        int r0 = m0 + wm0 + mi * 16 + g;
        int r1 = r0 + 8;
        float w0 = (r0 < cnt) ? g_wt[e * CAP + r0] : 0.f;
        float w1 = (r1 < cnt) ? g_wt[e * CAP + r1] : 0.f;
        #pragma unroll
        for (int ni = 0; ni < 4; ni++) {
            int col = n0 + wn0 + ni * 8 + tc;
            if (r0 < cnt) {
                float2 v = make_float2(acc[mi][ni][0] * w0, acc[mi][ni][1] * w0);
                *(float2*)(g_down + ((size_t)e * CAP + r0) * HID + col) = v;
            }
            if (r1 < cnt) {
                float2 v = make_float2(acc[mi][ni][2] * w1, acc[mi][ni][3] * w1);
                *(float2*)(g_down + ((size_t)e * CAP + r1) * HID + col) = v;
            }
        }
    }
}

// ---------------- 5) deterministic per-token combine ----------------
__global__ void combine_kernel(float* __restrict__ y) {
    int t = blockIdx.x;
    __shared__ int rows[NEXP];
    if (threadIdx.x < NEXP) rows[threadIdx.x] = g_rowid[threadIdx.x * T_TOK + t];
    __syncthreads();
    int h0 = threadIdx.x * 8;
    const float* sh = g_down + ((size_t)NEXP * CAP + t) * HID + h0;
    float4 s0 = *(const float4*)sh;
    float4 s1 = *(const float4*)(sh + 4);
    for (int e = 0; e < NEXP; e++) {
        int r = rows[e];
        if (r >= 0) {
            const float* p = g_down + (size_t)r * HID + h0;
            float4 a = *(const float4*)p;
            float4 b = *(const float4*)(p + 4);
            s0.x += a.x; s0.y += a.y; s0.z += a.z; s0.w += a.w;
            s1.x += b.x; s1.y += b.y; s1.z += b.z; s1.w += b.w;
        }
    }
    float* out = y + (size_t)t * HID + h0;
    *(float4*)out = s0;
    *(float4*)(out + 4) = s1;
}

// ---------------- launcher ----------------
extern "C" void kernel_launch(void* const* d_in, const int* in_sizes, int n_in,
                              void* d_out, int out_size) {
    const float* x    = (const float*)d_in[0];
    const float* gw   = (const float*)d_in[1];
    const float* bias = (const float*)d_in[2];
    const float* wgu  = (const float*)d_in[3];
    const float* wdn  = (const float*)d_in[4];
    const float* sgu  = (const float*)d_in[5];
    const float* sdn  = (const float*)d_in[6];
    float* y = (float*)d_out;

    cudaFuncSetAttribute(gateup_mma, cudaFuncAttributeMaxDynamicSharedMemorySize, SMEMB);
    cudaFuncSetAttribute(down_mma, cudaFuncAttributeMaxDynamicSharedMemorySize, SMEMB);

    router_kernel<<<T_TOK, 256>>>(x, gw, bias);
    build_lists_kernel<<<NE, T_TOK>>>();
    dim3 ga(CAP / 128, IDIM / 64, NE);
    gateup_mma<<<ga, 512, SMEMB>>>(x, wgu, sgu);
    dim3 gd(CAP / 128, HID / 128, NE);
    down_mma<<<gd, 512, SMEMB>>>(wdn, sdn);
    combine_kernel<<<T_TOK, 256>>>(y);
}

// round 13
// speedup vs baseline: 2.1220x; 2.1220x over previous
#include <cuda_runtime.h>
#include <cuda_fp16.h>
#include <cstdint>
#include <cstddef>

#define T_TOK 1024
#define HID   2048
#define IDIM  1024
#define NEXP  32
#define NGRP  8
#define EPG   4
#define TOPG  4
#define TOPK  8
#define NE    33      // 32 routed + 1 shared
#define CAP   1024
#define RSCALE 2.5f

// GEMM tiling: CTA 128x128, 8 warps of 64x32, BK=32, double buffer, cp.async A
#define BK    32
#define STR   40                 // padded fp16 row stride (80B, conflict-free ldmatrix)
#define TILEB (128 * STR * 2)    // 10240 bytes per 128xBK fp16 tile
#define BUFB  (2 * TILEB)        // A + B = 20480
#define SMEMB (2 * BUFB)         // double buffer = 40960

// ---------------- static scratch (no allocations allowed) ----------------
__device__ float  g_combine[T_TOK * NEXP];
__device__ int    g_count[NE];
__device__ int    g_token[NE * CAP];
__device__ float  g_wt[NE * CAP];
__device__ int    g_rowid[NEXP * T_TOK];                    // [e][t] -> row or -1
__device__ __half g_xh[(size_t)T_TOK * HID];                // x in fp16
__device__ __half g_act[(size_t)NE * CAP * IDIM];           // silu(g)*u rows (fp16)
__device__ float  g_down[(size_t)NE * CAP * HID];           // weighted down-proj rows

__device__ __forceinline__ float silu_f(float v) {
    return v / (1.0f + expf(-v));
}

__device__ __forceinline__ uint32_t smem_u32(const void* p) {
    uint32_t a;
    asm("{ .reg .u64 t; cvta.to.shared.u64 t, %1; cvt.u32.u64 %0, t; }"
        : "=r"(a) : "l"(p));
    return a;
}

__device__ __forceinline__ void ldm4(uint32_t* r, uint32_t addr) {
    asm volatile("ldmatrix.sync.aligned.m8n8.x4.shared.b16 {%0,%1,%2,%3}, [%4];"
        : "=r"(r[0]), "=r"(r[1]), "=r"(r[2]), "=r"(r[3]) : "r"(addr));
}
__device__ __forceinline__ void mma16816h(float* c, const uint32_t* a, const uint32_t* b) {
    asm volatile("mma.sync.aligned.m16n8k16.row.col.f32.f16.f16.f32 "
        "{%0,%1,%2,%3}, {%4,%5,%6,%7}, {%8,%9}, {%0,%1,%2,%3};"
        : "+f"(c[0]), "+f"(c[1]), "+f"(c[2]), "+f"(c[3])
        : "r"(a[0]), "r"(a[1]), "r"(a[2]), "r"(a[3]), "r"(b[0]), "r"(b[1]));
}

// fp32x4 -> fp16, store 8B
__device__ __forceinline__ void store_h(uint32_t a, float4 v) {
    __half h0 = __float2half_rn(v.x), h1 = __float2half_rn(v.y);
    __half h2 = __float2half_rn(v.z), h3 = __float2half_rn(v.w);
    unsigned long long H =
        (unsigned long long)__half_as_ushort(h0) |
        ((unsigned long long)__half_as_ushort(h1) << 16) |
        ((unsigned long long)__half_as_ushort(h2) << 32) |
        ((unsigned long long)__half_as_ushort(h3) << 48);
    asm volatile("st.shared.b64 [%0], %1;" :: "r"(a), "l"(H) : "memory");
}

#define CP_ASYNC16(dst, src) \
    asm volatile("cp.async.ca.shared.global [%0], [%1], 16;" :: "r"(dst), "l"(src) : "memory")
#define CP_COMMIT() asm volatile("cp.async.commit_group;" ::: "memory")
#define CP_WAIT0()  asm volatile("cp.async.wait_group 0;" ::: "memory")

// ---------------- 0) x -> fp16 prepass ----------------
__global__ void xcvt_kernel(const float* __restrict__ x) {
    size_t i = ((size_t)blockIdx.x * blockDim.x + threadIdx.x) * 4;
    float4 v = *(const float4*)(x + i);
    __half2* o = (__half2*)(g_xh + i);
    o[0] = __floats2half2_rn(v.x, v.y);
    o[1] = __floats2half2_rn(v.z, v.w);
}

// ---------------- 1) router ----------------
__global__ void router_kernel(const float* __restrict__ x,
                              const float* __restrict__ gw,
                              const float* __restrict__ bias) {
    __shared__ float sx[HID];
    __shared__ float slog[NEXP];
    int t = blockIdx.x;
    const float* xr = x + (size_t)t * HID;
    for (int k = threadIdx.x; k < HID; k += blockDim.x) sx[k] = xr[k];
    __syncthreads();
    int warp = threadIdx.x >> 5, lane = threadIdx.x & 31;
    for (int e = warp; e < NEXP; e += 8) {
        const float* w = gw + (size_t)e * HID;
        float acc = 0.f;
        for (int k = lane; k < HID; k += 32) acc = fmaf(sx[k], w[k], acc);
        #pragma unroll
        for (int o = 16; o; o >>= 1) acc += __shfl_down_sync(0xffffffffu, acc, o);
        if (lane == 0) slog[e] = acc;
    }
    __syncthreads();
    if (threadIdx.x == 0) {
        float s[NEXP], sr[NEXP];
        #pragma unroll
        for (int e = 0; e < NEXP; e++) {
            float sc = 1.f / (1.f + expf(-slog[e]));
            s[e] = sc;
            sr[e] = sc + bias[e];
        }
        float gs[NGRP];
        #pragma unroll
        for (int g = 0; g < NGRP; g++) {
            float m1 = -1e30f, m2 = -1e30f;
            #pragma unroll
            for (int j = 0; j < EPG; j++) {
                float v = sr[g * EPG + j];
                if (v > m1) { m2 = m1; m1 = v; }
                else if (v > m2) { m2 = v; }
            }
            gs[g] = m1 + m2;
        }
        bool gsel[NGRP];
        #pragma unroll
        for (int g = 0; g < NGRP; g++) gsel[g] = false;
        for (int it = 0; it < TOPG; it++) {
            float best = -1e30f; int bi = 0;
            for (int g = 0; g < NGRP; g++)
                if (!gsel[g] && gs[g] > best) { best = gs[g]; bi = g; }
            gsel[bi] = true;
        }
        bool taken[NEXP];
        #pragma unroll
        for (int e = 0; e < NEXP; e++) taken[e] = false;
        int ids[TOPK];
        for (int it = 0; it < TOPK; it++) {
            float best = -1e30f; int bi = 0;
            for (int e = 0; e < NEXP; e++)
                if (gsel[e >> 2] && !taken[e] && sr[e] > best) { best = sr[e]; bi = e; }
            taken[bi] = true;
            ids[it] = bi;
        }
        float sum = 0.f;
        for (int k = 0; k < TOPK; k++) sum += s[ids[k]];
        float inv = RSCALE / (sum + 1e-20f);
        float out[NEXP];
        #pragma unroll
        for (int e = 0; e < NEXP; e++) out[e] = 0.f;
        for (int k = 0; k < TOPK; k++) out[ids[k]] = s[ids[k]] * inv;
        #pragma unroll
        for (int e = 0; e < NEXP; e++) g_combine[t * NEXP + e] = out[e];
    }
}

// ---------------- 2) compact per-expert token lists ----------------
__global__ void build_lists_kernel() {
    int e = blockIdx.x;
    int t = threadIdx.x;
    __shared__ int sc[T_TOK];
    float w;
    int flag;
    if (e < NEXP) {
        w = g_combine[t * NEXP + e];
        flag = (w > 0.f) ? 1 : 0;
    } else {
        w = 1.0f;
        flag = 1;
    }
    sc[t] = flag;
    __syncthreads();
    for (int off = 1; off < T_TOK; off <<= 1) {
        int v = (t >= off) ? sc[t - off] : 0;
        __syncthreads();
        sc[t] += v;
        __syncthreads();
    }
    int pos = sc[t] - flag;
    if (flag) {
        g_token[e * CAP + pos] = t;
        g_wt[e * CAP + pos] = w;
    }
    if (e < NEXP) g_rowid[e * T_TOK + t] = flag ? (e * CAP + pos) : -1;
    if (t == T_TOK - 1) g_count[e] = sc[T_TOK - 1];
}

// ---------------- 3) gate_up GEMM: fp16 mma, cp.async A, 64x32 warps -------
// CTA tile: M=128 rows, D = 128 cols interleaved (even=gate j, odd=up j).
__global__ void __launch_bounds__(256, 2)
gateup_mma(const float* __restrict__ wgu,
           const float* __restrict__ sgu) {
    int e = blockIdx.z;
    int cnt = g_count[e];
    int m0 = blockIdx.x * 128;
    if (m0 >= cnt) return;
    int n0 = blockIdx.y * 64;
    const float* W = (e < NEXP) ? (wgu + (size_t)e * (2 * IDIM) * HID) : sgu;

    extern __shared__ char smem[];
    uint32_t sb = smem_u32(smem);
    int tid = threadIdx.x;
    int lane = tid & 31, wid = tid >> 5;

    // A cp.async mapping: 512 ops of 16B (128 rows x 4 segs); thread does ops tid, tid+256
    int ar0 = tid >> 2, as0 = tid & 3;        // op tid
    int ar1 = 64 + ar0;                        // op tid+256 (same seg)
    int mr0 = m0 + ar0; if (mr0 > cnt - 1) mr0 = cnt - 1;
    int mr1 = m0 + ar1; if (mr1 > cnt - 1) mr1 = cnt - 1;
    const __half* asrc0 = g_xh + (size_t)g_token[e * CAP + mr0] * HID + as0 * 8;
    const __half* asrc1 = g_xh + (size_t)g_token[e * CAP + mr1] * HID + as0 * 8;
    uint32_t adst0 = (uint32_t)(ar0 * STR + as0 * 8) * 2;
    uint32_t adst1 = (uint32_t)(ar1 * STR + as0 * 8) * 2;

    // B loader: 2 threads per row, 16 floats each
    int lrow = tid >> 1, lhalf = tid & 1;
    int jcol = lrow >> 1;
    int wrow = (lrow & 1) ? (IDIM + n0 + jcol) : (n0 + jcol);
    const float* bptr = W + (size_t)wrow * HID + lhalf * 16;
    uint32_t bdst = TILEB + (uint32_t)(lrow * STR + lhalf * 16) * 2;

    // warp grid 2x4: each warp 64 rows x 32 cols
    int wm0 = (wid >> 2) * 64, wn0 = (wid & 3) * 32;
    uint32_t a_r = (uint32_t)(wm0 + (lane & 15));
    uint32_t a_c8 = (uint32_t)((lane >> 4) * 8);
    uint32_t b_row = (uint32_t)((lane & 7) + ((lane >> 4) << 3));
    uint32_t b_k8 = (uint32_t)(((lane >> 3) & 1) * 8);

    float acc[4][4][4];
    #pragma unroll
    for (int mi = 0; mi < 4; mi++)
        #pragma unroll
        for (int ni = 0; ni < 4; ni++)
            #pragma unroll
            for (int q = 0; q < 4; q++) acc[mi][ni][q] = 0.f;

    float4 rb[4];
    // prologue: chunk 0
    CP_ASYNC16(sb + adst0, asrc0);
    CP_ASYNC16(sb + adst1, asrc1);
    CP_COMMIT();
    #pragma unroll
    for (int q = 0; q < 4; q++) rb[q] = *(const float4*)(bptr + q * 4);
    #pragma unroll
    for (int q = 0; q < 4; q++) store_h(sb + bdst + q * 8, rb[q]);
    CP_WAIT0();
    __syncthreads();

    const int NC = HID / BK;  // 64
    for (int c = 0; c < NC; c++) {
        if (c + 1 < NC) {
            uint32_t nb = sb + (uint32_t)((c + 1) & 1) * BUFB;
            CP_ASYNC16(nb + adst0, asrc0 + (c + 1) * BK);
            CP_ASYNC16(nb + adst1, asrc1 + (c + 1) * BK);
            CP_COMMIT();
            const float* bp = bptr + (c + 1) * BK;
            #pragma unroll
            for (int q = 0; q < 4; q++) rb[q] = *(const float4*)(bp + q * 4);
        }
        uint32_t cur = sb + (uint32_t)(c & 1) * BUFB;
        #pragma unroll
        for (int kh = 0; kh < 2; kh++) {
            uint32_t ah[4][4], bh[2][4];
            #pragma unroll
            for (int mi = 0; mi < 4; mi++) {
                uint32_t ad = cur + ((a_r + mi * 16) * STR + kh * 16 + a_c8) * 2;
                ldm4(ah[mi], ad);
            }
            #pragma unroll
            for (int nj = 0; nj < 2; nj++) {
                uint32_t bd = cur + TILEB +
                    ((wn0 + nj * 16 + b_row) * STR + kh * 16 + b_k8) * 2;
                ldm4(bh[nj], bd);
            }
            #pragma unroll
            for (int mi = 0; mi < 4; mi++)
                #pragma unroll
                for (int ni = 0; ni < 4; ni++) {
                    const uint32_t* bhp = &bh[ni >> 1][(ni & 1) * 2];
                    mma16816h(acc[mi][ni], ah[mi], bhp);
                }
        }
        if (c + 1 < NC) {
            uint32_t nb = sb + (uint32_t)((c + 1) & 1) * BUFB;
            #pragma unroll
            for (int q = 0; q < 4; q++) store_h(nb + bdst + q * 8, rb[q]);
        }
        CP_WAIT0();
        __syncthreads();
    }

    // epilogue: c0=gate, c1=up for col j; rows g and g+8 -> fp16 g_act
    int g = lane >> 2, tc = (lane & 3) * 2;
    #pragma unroll
    for (int mi = 0; mi < 4; mi++) {
        int r0 = m0 + wm0 + mi * 16 + g;
        int r1 = r0 + 8;
        #pragma unroll
        for (int ni = 0; ni < 4; ni++) {
            int col = n0 + ((wn0 + ni * 8 + tc) >> 1);
            if (r0 < cnt)
                g_act[((size_t)e * CAP + r0) * IDIM + col] =
                    __float2half_rn(silu_f(acc[mi][ni][0]) * acc[mi][ni][1]);
            if (r1 < cnt)
                g_act[((size_t)e * CAP + r1) * IDIM + col] =
                    __float2half_rn(silu_f(acc[mi][ni][2]) * acc[mi][ni][3]);
        }
    }
}

// ---------------- 4) down GEMM: fp16 mma, cp.async A, 64x32 warps ----------
__global__ void __launch_bounds__(256, 2)
down_mma(const float* __restrict__ wdn,
         const float* __restrict__ sdn) {
    int e = blockIdx.z;
    int cnt = g_count[e];
    int m0 = blockIdx.x * 128;
    if (m0 >= cnt) return;
    int n0 = blockIdx.y * 128;
    const float* W = (e < NEXP) ? (wdn + (size_t)e * HID * IDIM) : sdn;

    extern __shared__ char smem[];
    uint32_t sb = smem_u32(smem);
    int tid = threadIdx.x;
    int lane = tid & 31, wid = tid >> 5;

    int ar0 = tid >> 2, as0 = tid & 3;
    int ar1 = 64 + ar0;
    int mr0 = m0 + ar0; if (mr0 > cnt - 1) mr0 = cnt - 1;
    int mr1 = m0 + ar1; if (mr1 > cnt - 1) mr1 = cnt - 1;
    const __half* asrc0 = g_act + ((size_t)e * CAP + mr0) * IDIM + as0 * 8;
    const __half* asrc1 = g_act + ((size_t)e * CAP + mr1) * IDIM + as0 * 8;
    uint32_t adst0 = (uint32_t)(ar0 * STR + as0 * 8) * 2;
    uint32_t adst1 = (uint32_t)(ar1 * STR + as0 * 8) * 2;

    int lrow = tid >> 1, lhalf = tid & 1;
    const float* bptr = W + (size_t)(n0 + lrow) * IDIM + lhalf * 16;
    uint32_t bdst = TILEB + (uint32_t)(lrow * STR + lhalf * 16) * 2;

    int wm0 = (wid >> 2) * 64, wn0 = (wid & 3) * 32;
    uint32_t a_r = (uint32_t)(wm0 + (lane & 15));
    uint32_t a_c8 = (uint32_t)((lane >> 4) * 8);
    uint32_t b_row = (uint32_t)((lane & 7) + ((lane >> 4) << 3));
    uint32_t b_k8 = (uint32_t)(((lane >> 3) & 1) * 8);

    float acc[4][4][4];
    #pragma unroll
    for (int mi = 0; mi < 4; mi++)
        #pragma unroll
        for (int ni = 0; ni < 4; ni++)
            #pragma unroll
            for (int q = 0; q < 4; q++) acc[mi][ni][q] = 0.f;

    float4 rb[4];
    CP_ASYNC16(sb + adst0, asrc0);
    CP_ASYNC16(sb + adst1, asrc1);
    CP_COMMIT();
    #pragma unroll
    for (int q = 0; q < 4; q++) rb[q] = *(const float4*)(bptr + q * 4);
    #pragma unroll
    for (int q = 0; q < 4; q++) store_h(sb + bdst + q * 8, rb[q]);
    CP_WAIT0();
    __syncthreads();

    const int NC = IDIM / BK;  // 32
    for (int c = 0; c < NC; c++) {
        if (c + 1 < NC) {
            uint32_t nb = sb + (uint32_t)((c + 1) & 1) * BUFB;
            CP_ASYNC16(nb + adst0, asrc0 + (c + 1) * BK);
            CP_ASYNC16(nb + adst1, asrc1 + (c + 1) * BK);
            CP_COMMIT();
            const float* bp = bptr + (c + 1) * BK;
            #pragma unroll
            for (int q = 0; q < 4; q++) rb[q] = *(const float4*)(bp + q * 4);
        }
        uint32_t cur = sb + (uint32_t)(c & 1) * BUFB;
        #pragma unroll
        for (int kh = 0; kh < 2; kh++) {
            uint32_t ah[4][4], bh[2][4];
            #pragma unroll
            for (int mi = 0; mi < 4; mi++) {
                uint32_t ad = cur + ((a_r + mi * 16) * STR + kh * 16 + a_c8) * 2;
                ldm4(ah[mi], ad);
            }
            #pragma unroll
            for (int nj = 0; nj < 2; nj++) {
                uint32_t bd = cur + TILEB +
                    ((wn0 + nj * 16 + b_row) * STR + kh * 16 + b_k8) * 2;
                ldm4(bh[nj], bd);
            }
            #pragma unroll
            for (int mi = 0; mi < 4; mi++)
                #pragma unroll
                for (int ni = 0; ni < 4; ni++) {
                    const uint32_t* bhp = &bh[ni >> 1][(ni & 1) * 2];
                    mma16816h(acc[mi][ni], ah[mi], bhp);
                }
        }
        if (c + 1 < NC) {
            uint32_t nb = sb + (uint32_t)((c + 1) & 1) * BUFB;
            #pragma unroll
            for (int q = 0; q < 4; q++) store_h(nb + bdst + q * 8, rb[q]);
        }
        CP_WAIT0();
        __syncthreads();
    }

    int g = lane >> 2, tc = (lane & 3) * 2;
    #pragma unroll
    for (int mi = 0; mi < 4; mi++) {
        int r0 = m0 + wm0 + mi * 16 + g;
        int r1 = r0 + 8;
        float w0 = (r0 < cnt) ? g_wt[e * CAP + r0] : 0.f;
        float w1 = (r1 < cnt) ? g_wt[e * CAP + r1] : 0.f;
        #pragma unroll
        for (int ni = 0; ni < 4; ni++) {
            int col = n0 + wn0 + ni * 8 + tc;
            if (r0 < cnt) {
                float2 v = make_float2(acc[mi][ni][0] * w0, acc[mi][ni][1] * w0);
                *(float2*)(g_down + ((size_t)e * CAP + r0) * HID + col) = v;
            }
            if (r1 < cnt) {
                float2 v = make_float2(acc[mi][ni][2] * w1, acc[mi][ni][3] * w1);
                *(float2*)(g_down + ((size_t)e * CAP + r1) * HID + col) = v;
            }
        }
    }
}

// ---------------- 5) deterministic per-token combine ----------------
__global__ void combine_kernel(float* __restrict__ y) {
    int t = blockIdx.x;
    __shared__ int rows[NEXP];
    if (threadIdx.x < NEXP) rows[threadIdx.x] = g_rowid[threadIdx.x * T_TOK + t];
    __syncthreads();
    int h0 = threadIdx.x * 8;
    const float* sh = g_down + ((size_t)NEXP * CAP + t) * HID + h0;
    float4 s0 = *(const float4*)sh;
    float4 s1 = *(const float4*)(sh + 4);
    for (int e = 0; e < NEXP; e++) {
        int r = rows[e];
        if (r >= 0) {
            const float* p = g_down + (size_t)r * HID + h0;
            float4 a = *(const float4*)p;
            float4 b = *(const float4*)(p + 4);
            s0.x += a.x; s0.y += a.y; s0.z += a.z; s0.w += a.w;
            s1.x += b.x; s1.y += b.y; s1.z += b.z; s1.w += b.w;
        }
    }
    float* out = y + (size_t)t * HID + h0;
    *(float4*)out = s0;
    *(float4*)(out + 4) = s1;
}

// ---------------- launcher ----------------
extern "C" void kernel_launch(void* const* d_in, const int* in_sizes, int n_in,
                              void* d_out, int out_size) {
    const float* x    = (const float*)d_in[0];
    const float* gw   = (const float*)d_in[1];
    const float* bias = (const float*)d_in[2];
    const float* wgu  = (const float*)d_in[3];
    const float* wdn  = (const float*)d_in[4];
    const float* sgu  = (const float*)d_in[5];
    const float* sdn  = (const float*)d_in[6];
    float* y = (float*)d_out;

    xcvt_kernel<<<(T_TOK * HID) / (256 * 4), 256>>>(x);
    router_kernel<<<T_TOK, 256>>>(x, gw, bias);
    build_lists_kernel<<<NE, T_TOK>>>();
    dim3 ga(CAP / 128, IDIM / 64, NE);
    gateup_mma<<<ga, 256, SMEMB>>>(wgu, sgu);
    dim3 gd(CAP / 128, HID / 128, NE);
    down_mma<<<gd, 256, SMEMB>>>(wdn, sdn);
    combine_kernel<<<T_TOK, 256>>>(y);
}